// round 14
// baseline (speedup 1.0000x reference)
#include <cuda_runtime.h>
#include <cuda_bf16.h>
#include <math.h>
#include <stdint.h>

// Shape fixed by reference: B=2, C=512, H=W=64 -> N=4096, 32 groups.
#define BATCH 2
#define CCH   512
#define NGRP  32
#define NPIX  4096
#define EPSV  1e-6f

// ---------------------------------------------------------------------------
// Scratch
// ---------------------------------------------------------------------------
__device__ __nv_bfloat16 g_wb  [4 * CCH * CCH];
__device__ float         g_bqkv[3 * CCH];
__device__ __nv_bfloat16 g_hb  [BATCH * CCH * NPIX];
__device__ __nv_bfloat16 g_qkv [BATCH * 3 * CCH * NPIX];
__device__ __nv_bfloat16 g_ab  [(size_t)BATCH * NPIX * NPIX];
__device__ __nv_bfloat16 g_aob [BATCH * CCH * NPIX];
__device__ float         g_part[(size_t)BATCH * NPIX * 32];
__device__ float         g_inv [BATCH * NPIX];
__device__ float2        g_gp  [64 * 8];    // groupnorm partial {sum, sumsq}
__device__ float2        g_gs  [64];        // groupnorm {mean, inv}

// ---------------------------------------------------------------------------
// Helpers
// ---------------------------------------------------------------------------
__device__ __forceinline__ float warpSum(float v) {
    #pragma unroll
    for (int o = 16; o; o >>= 1) v += __shfl_xor_sync(0xffffffffu, v, o);
    return v;
}
__device__ __forceinline__ uint32_t pack_bf16(float lo, float hi) {
    uint32_t u;
    asm("cvt.rn.bf16x2.f32 %0, %1, %2;" : "=r"(u) : "f"(hi), "f"(lo));
    return u;
}
__device__ __forceinline__ void ldsm4(uint32_t& r0, uint32_t& r1,
                                      uint32_t& r2, uint32_t& r3, uint32_t addr) {
    asm volatile("ldmatrix.sync.aligned.x4.m8n8.shared.b16 {%0,%1,%2,%3},[%4];"
                 : "=r"(r0), "=r"(r1), "=r"(r2), "=r"(r3) : "r"(addr));
}
__device__ __forceinline__ void ldsm4t(uint32_t& r0, uint32_t& r1,
                                       uint32_t& r2, uint32_t& r3, uint32_t addr) {
    asm volatile("ldmatrix.sync.aligned.x4.m8n8.trans.shared.b16 {%0,%1,%2,%3},[%4];"
                 : "=r"(r0), "=r"(r1), "=r"(r2), "=r"(r3) : "r"(addr));
}
__device__ __forceinline__ void cpasync16(uint32_t smem, const void* g) {
    asm volatile("cp.async.cg.shared.global [%0],[%1],16;" :: "r"(smem), "l"(g));
}
#define CP_COMMIT() asm volatile("cp.async.commit_group;")

// ---------------------------------------------------------------------------
// Weights fp32 -> bf16; last 6 blocks also build the stacked qkv bias
// ---------------------------------------------------------------------------
__global__ __launch_bounds__(256) void cvtw_kernel(
    const float* __restrict__ wq, const float* __restrict__ wk,
    const float* __restrict__ wv, const float* __restrict__ wo,
    const float* __restrict__ bq, const float* __restrict__ bk,
    const float* __restrict__ bv,
    __nv_bfloat16* __restrict__ dst, float* __restrict__ bd)
{
    int b = blockIdx.x;
    if (b >= 512) {
        int i = (b - 512) * 256 + threadIdx.x;
        bd[i] = (i < 512) ? bq[i] : (i < 1024) ? bk[i - 512] : bv[i - 1024];
        return;
    }
    int mi = b >> 7, blk = b & 127;
    const float* src = (mi == 0) ? wq : (mi == 1) ? wk : (mi == 2) ? wv : wo;
    const float4* s4 = (const float4*)src;
    uint2* d2 = (uint2*)(dst + (size_t)mi * CCH * CCH);
    #pragma unroll
    for (int t = 0; t < 2; t++) {
        int i = blk * 512 + threadIdx.x + t * 256;
        float4 v = s4[i];
        d2[i] = make_uint2(pack_bf16(v.x, v.y), pack_bf16(v.z, v.w));
    }
}

__global__ __launch_bounds__(256) void rowinv_kernel(
    const float* __restrict__ part, float* __restrict__ inv)
{
    int r = blockIdx.x * 256 + threadIdx.x;
    const float* p = part + (size_t)r * 32;
    float s = 0.f;
    #pragma unroll
    for (int i = 0; i < 32; i++) s += p[i];
    inv[r] = 1.f / s;
}

// ---------------------------------------------------------------------------
// GroupNorm, three-phase (full-grid, deterministic) — R13-proven
// ---------------------------------------------------------------------------
__global__ __launch_bounds__(256) void gn_stats1(
    const float* __restrict__ x, float2* __restrict__ gp)
{
    int bg = blockIdx.x;
    int g64 = bg >> 3, slice = bg & 7;
    size_t base = (size_t)g64 * 16 * NPIX + (size_t)slice * 8192;
    const float4* x4 = (const float4*)(x + base);
    int tid = threadIdx.x;
    float s = 0.f, ss = 0.f;
    #pragma unroll
    for (int t = 0; t < 8; t++) {
        float4 v = x4[tid + t * 256];
        s  += v.x + v.y + v.z + v.w;
        ss += v.x * v.x + v.y * v.y + v.z * v.z + v.w * v.w;
    }
    __shared__ float rs[8], rss[8];
    float ws = warpSum(s), wss = warpSum(ss);
    int lane = tid & 31, wid = tid >> 5;
    if (lane == 0) { rs[wid] = ws; rss[wid] = wss; }
    __syncthreads();
    if (tid == 0) {
        float S = 0.f, SS = 0.f;
        #pragma unroll
        for (int i = 0; i < 8; i++) { S += rs[i]; SS += rss[i]; }
        gp[bg] = make_float2(S, SS);
    }
}

__global__ __launch_bounds__(64) void gn_stats2(
    const float2* __restrict__ gp, float2* __restrict__ gs)
{
    int g64 = threadIdx.x;
    float S = 0.f, SS = 0.f;
    #pragma unroll
    for (int i = 0; i < 8; i++) {
        float2 p = gp[g64 * 8 + i];
        S += p.x; SS += p.y;
    }
    const float GSZ = 16.f * NPIX;
    float mean = S / GSZ;
    float var = SS / GSZ - mean * mean;
    gs[g64] = make_float2(mean, rsqrtf(var + EPSV));
}

__global__ __launch_bounds__(256) void gn_norm(
    const float* __restrict__ x, const float* __restrict__ w,
    const float* __restrict__ b, const float2* __restrict__ gs,
    __nv_bfloat16* __restrict__ out)
{
    int bg = blockIdx.x;
    int g64 = bg >> 3, slice = bg & 7;
    int g = g64 & 31;
    size_t base = (size_t)g64 * 16 * NPIX + (size_t)slice * 8192;
    const float4* x4 = (const float4*)(x + base);
    uint2* o2 = (uint2*)(out + base);
    float2 mv = gs[g64];
    int c0 = g * 16 + slice * 2;
    float sc0 = w[c0] * mv.y,     sb0 = b[c0] - mv.x * sc0;
    float sc1 = w[c0 + 1] * mv.y, sb1 = b[c0 + 1] - mv.x * sc1;
    int tid = threadIdx.x;
    #pragma unroll
    for (int t = 0; t < 8; t++) {
        int i = tid + t * 256;
        float sc = (i < 1024) ? sc0 : sc1;
        float sb = (i < 1024) ? sb0 : sb1;
        float4 v = x4[i];
        v.x = v.x * sc + sb; v.y = v.y * sc + sb;
        v.z = v.z * sc + sb; v.w = v.w * sc + sb;
        o2[i] = make_uint2(pack_bf16(v.x, v.y), pack_bf16(v.z, v.w));
    }
}

// ---------------------------------------------------------------------------
// BF16 tensor-core GEMM, BK=64, 4-stage cp.async pipeline (depth 3) with
// register-level fragment double-buffering. __launch_bounds__(256,1) gives
// ptxas the register headroom (~150-180) to keep BOTH fragment sets live
// (the R12 attempt was silently collapsed by the 2-CTA/SM 126-reg cap).
//   C[m,n] = alpha * sum_k A(m,k)*B(k,n)
//   TA/TB layouts; OBF bf16 out; BIAS +bias[m]; RES +resid
//   EXPO: C = bf16(exp(alpha*acc)) + per-row partial sums
//   SCL : epilogue multiply by scl[n]
// Block 128x128, 256 threads (8 warps, warp tile 64x32).
// smem strides (halves): k-contig [128][64] stride 72; m/n-contig [64][128]
// stride 136. Both conflict-free for LDSM.
// ---------------------------------------------------------------------------
#define BM 128
#define BN 128
#define BK 64
#define STAGES 4
#define TILE_H 9216
#define SMEMSZ (STAGES * TILE_H * 2 * 2)   // 147456 bytes

#define MMA_BF16(d, a, b)                                                     \
    asm volatile(                                                             \
        "mma.sync.aligned.m16n8k16.row.col.f32.bf16.bf16.f32 "                \
        "{%0,%1,%2,%3},{%4,%5,%6,%7},{%8,%9},{%0,%1,%2,%3};"                  \
        : "+f"(d[0]), "+f"(d[1]), "+f"(d[2]), "+f"(d[3])                      \
        : "r"(a[0]), "r"(a[1]), "r"(a[2]), "r"(a[3]), "r"(b[0]), "r"(b[1]))

template<int TA, int TB, bool BIAS, bool RES, bool OBF, bool EXPO, bool SCL>
__global__ __launch_bounds__(256, 1) void bgemm_kernel(
    const __nv_bfloat16* __restrict__ A, int lda, size_t sA,
    const __nv_bfloat16* __restrict__ B, int ldb, size_t sB,
    void* __restrict__ Cv, int ldc, size_t sC,
    const float* __restrict__ bias,
    const float* __restrict__ resid, size_t sR,
    float* __restrict__ part, const float* __restrict__ scl,
    int K, float alpha)
{
    extern __shared__ __align__(16) uint16_t dsm[];
    uint16_t* Asm = dsm;
    uint16_t* Bsm = dsm + STAGES * TILE_H;

    int bz = blockIdx.z;
    A += (size_t)bz * sA;
    B += (size_t)bz * sB;
    if (RES) resid += (size_t)bz * sR;
    if (SCL) scl   += (size_t)bz * NPIX;

    const int m0 = blockIdx.y * BM;
    const int n0 = blockIdx.x * BN;
    const int tid = threadIdx.x;
    const int lane = tid & 31;
    const int warp = tid >> 5;
    const int wm = warp >> 2;
    const int wn = warp & 3;
    const int R  = wm * 64;
    const int CN = wn * 32;

    const uint32_t aS0 = (uint32_t)__cvta_generic_to_shared(Asm);
    const uint32_t bS0 = (uint32_t)__cvta_generic_to_shared(Bsm);

    // ---- staging: 4 x 16B chunks per operand per thread (tile = 16KB data) ----
    size_t gA[4]; int soA[4];
    size_t gB[4]; int soB[4];
    #pragma unroll
    for (int t = 0; t < 4; t++) {
        int f = tid + t * 256;
        if (TA == 0) {                         // [128][64] k-contig, stride 72
            int m = f >> 3, c8 = (f & 7) << 3;
            gA[t] = (size_t)(m0 + m) * lda + c8;
            soA[t] = m * 72 + c8;
        } else {                               // [64][128] m-contig, stride 136
            int k = f >> 4, c8 = (f & 15) << 3;
            gA[t] = (size_t)k * lda + m0 + c8;
            soA[t] = k * 136 + c8;
        }
        if (TB == 0) {                         // [64][128] n-contig, stride 136
            int k = f >> 4, c8 = (f & 15) << 3;
            gB[t] = (size_t)k * ldb + n0 + c8;
            soB[t] = k * 136 + c8;
        } else {                               // [128][64] k-contig, stride 72
            int n = f >> 3, c8 = (f & 7) << 3;
            gB[t] = (size_t)(n0 + n) * ldb + c8;
            soB[t] = n * 72 + c8;
        }
    }
    const size_t stepA = (TA == 0) ? (size_t)BK : (size_t)BK * lda;
    const size_t stepB = (TB == 0) ? (size_t)BK * ldb : (size_t)BK;

    // ---- lane-derived LDSM base offsets (halves) ----
    const int lq = lane & 7;
    const int b1 = (lane >> 3) & 1;
    const int b2 = lane >> 4;
    int aBase, bBase;
    if (TA == 0) aBase = (R + lq + 8 * b1) * 72 + 8 * b2;
    else         aBase = (lq + 8 * b2) * 136 + R + 8 * b1;
    if (TB == 0) bBase = (lq + 8 * b1) * 136 + CN + 8 * b2;
    else         bBase = (CN + lq + 8 * b2) * 72 + 8 * b1;

    float acc[4][4][4];
    #pragma unroll
    for (int i = 0; i < 4; i++)
        #pragma unroll
        for (int j = 0; j < 4; j++)
            #pragma unroll
            for (int r = 0; r < 4; r++) acc[i][j][r] = 0.f;

    const int KT = K / BK;

    // fragment loader for k-step ks from stage base (aS,bS)
    auto ldfrag = [&](int ks, uint32_t aS, uint32_t bS,
                      uint32_t af[4][4], uint32_t bf[4][2]) {
        #pragma unroll
        for (int mt = 0; mt < 4; mt++) {
            int off = (TA == 0) ? (aBase + mt * 1152 + ks * 16)
                                : (aBase + ks * 2176 + mt * 16);
            uint32_t addr = aS + 2 * off;
            if (TA == 0) ldsm4 (af[mt][0], af[mt][1], af[mt][2], af[mt][3], addr);
            else         ldsm4t(af[mt][0], af[mt][1], af[mt][2], af[mt][3], addr);
        }
        #pragma unroll
        for (int ntp = 0; ntp < 2; ntp++) {
            int off = (TB == 0) ? (bBase + ks * 2176 + ntp * 16)
                                : (bBase + ntp * 1152 + ks * 16);
            uint32_t addr = bS + 2 * off;
            if (TB == 0)
                ldsm4t(bf[ntp*2][0], bf[ntp*2][1], bf[ntp*2+1][0], bf[ntp*2+1][1], addr);
            else
                ldsm4 (bf[ntp*2][0], bf[ntp*2][1], bf[ntp*2+1][0], bf[ntp*2+1][1], addr);
        }
    };

    // ---- prologue: async-stage tiles 0..2 ----
    #pragma unroll
    for (int s = 0; s < 3; s++) {
        #pragma unroll
        for (int t = 0; t < 4; t++) {
            cpasync16(aS0 + (s * TILE_H + soA[t]) * 2, A + gA[t] + (size_t)s * stepA);
            cpasync16(bS0 + (s * TILE_H + soB[t]) * 2, B + gB[t] + (size_t)s * stepB);
        }
        CP_COMMIT();
    }

    for (int kt = 0; kt < KT; kt++) {
        const int cur = kt & 3;
        {
            const int rem = KT - 1 - kt;       // groups still in flight after this
            if (rem >= 2)      asm volatile("cp.async.wait_group 2;");
            else if (rem == 1) asm volatile("cp.async.wait_group 1;");
            else               asm volatile("cp.async.wait_group 0;");
        }
        __syncthreads();

        const uint32_t aS = aS0 + cur * (TILE_H * 2);
        const uint32_t bS = bS0 + cur * (TILE_H * 2);

        // register-level double-buffered fragments
        uint32_t a[2][4][4], b[2][4][2];
        ldfrag(0, aS, bS, a[0], b[0]);
        #pragma unroll
        for (int ks = 0; ks < 4; ks++) {
            if (ks < 3) ldfrag(ks + 1, aS, bS, a[(ks + 1) & 1], b[(ks + 1) & 1]);
            const int c = ks & 1;
            #pragma unroll
            for (int mt = 0; mt < 4; mt++)
                #pragma unroll
                for (int nt = 0; nt < 4; nt++)
                    MMA_BF16(acc[mt][nt], a[c][mt], b[c][nt]);
        }

        // stage kt+3 into buffer (kt+3)&3 (consumed at kt-1; safe after barrier)
        if (kt + 3 < KT) {
            const int nxt = (kt + 3) & 3;
            size_t ko = (size_t)(kt + 3);
            #pragma unroll
            for (int t = 0; t < 4; t++) {
                cpasync16(aS0 + (nxt * TILE_H + soA[t]) * 2, A + gA[t] + ko * stepA);
                cpasync16(bS0 + (nxt * TILE_H + soB[t]) * 2, B + gB[t] + ko * stepB);
            }
            CP_COMMIT();
        }
    }

    if (EXPO) {
        // scores epilogue: P = bf16(exp(alpha*acc)); deterministic row partials
        __syncthreads();
        float* spart = (float*)dsm;            // [128][4]
        __nv_bfloat16* Cb = (__nv_bfloat16*)Cv + (size_t)bz * sC;
        #pragma unroll
        for (int mt = 0; mt < 4; mt++) {
            int rbase = R + mt * 16 + (lane >> 2);
            #pragma unroll
            for (int h = 0; h < 2; h++) {
                int rowl = rbase + h * 8;
                int m = m0 + rowl;
                float rsum = 0.f;
                #pragma unroll
                for (int nt = 0; nt < 4; nt++) {
                    int n = n0 + CN + nt * 8 + 2 * (lane & 3);
                    float e0 = __expf(acc[mt][nt][h * 2 + 0] * alpha);
                    float e1 = __expf(acc[mt][nt][h * 2 + 1] * alpha);
                    rsum += e0 + e1;
                    *(uint32_t*)(Cb + (size_t)m * ldc + n) = pack_bf16(e0, e1);
                }
                rsum += __shfl_xor_sync(0xffffffffu, rsum, 1);
                rsum += __shfl_xor_sync(0xffffffffu, rsum, 2);
                if ((lane & 3) == 0) spart[rowl * 4 + wn] = rsum;
            }
        }
        __syncthreads();
        if (tid < 128) {
            float vv = spart[tid * 4] + spart[tid * 4 + 1]
                     + spart[tid * 4 + 2] + spart[tid * 4 + 3];
            part[((size_t)bz * NPIX + m0 + tid) * 32 + blockIdx.x] = vv;
        }
        return;
    }

    // ---- standard epilogue ----
    #pragma unroll
    for (int mt = 0; mt < 4; mt++) {
        int mA = m0 + R + mt * 16 + (lane >> 2);
        #pragma unroll
        for (int h = 0; h < 2; h++) {
            int m = mA + h * 8;
            float bi = BIAS ? bias[m] : 0.f;
            #pragma unroll
            for (int nt = 0; nt < 4; nt++) {
                int n = n0 + CN + nt * 8 + 2 * (lane & 3);
                size_t off = (size_t)m * ldc + n;
                float ox = acc[mt][nt][h * 2 + 0] * alpha + bi;
                float oy = acc[mt][nt][h * 2 + 1] * alpha + bi;
                if (SCL) { ox *= scl[n]; oy *= scl[n + 1]; }
                if (OBF) {
                    __nv_bfloat16* Cb = (__nv_bfloat16*)Cv + (size_t)bz * sC;
                    *(uint32_t*)(Cb + off) = pack_bf16(ox, oy);
                } else {
                    float* Cf = (float*)Cv + (size_t)bz * sC;
                    if (RES) {
                        float2 rr = *(const float2*)(resid + off);
                        ox += rr.x; oy += rr.y;
                    }
                    *(float2*)(Cf + off) = make_float2(ox, oy);
                }
            }
        }
    }
}

// ---------------------------------------------------------------------------
// Host launcher
// ---------------------------------------------------------------------------
extern "C" void kernel_launch(void* const* d_in, const int* in_sizes, int n_in,
                              void* d_out, int out_size)
{
    const float* x      = (const float*)d_in[0];
    const float* norm_w = (const float*)d_in[1];
    const float* norm_b = (const float*)d_in[2];
    const float* wq     = (const float*)d_in[3];
    const float* bq     = (const float*)d_in[4];
    const float* wk     = (const float*)d_in[5];
    const float* bk     = (const float*)d_in[6];
    const float* wv     = (const float*)d_in[7];
    const float* bv     = (const float*)d_in[8];
    const float* wo     = (const float*)d_in[9];
    const float* bo     = (const float*)d_in[10];
    float* out = (float*)d_out;

    __nv_bfloat16 *wb, *hb, *qkv, *ab, *aob;
    float *bqkv, *prt, *inv;
    float2 *gp, *gs;
    cudaGetSymbolAddress((void**)&wb,   g_wb);
    cudaGetSymbolAddress((void**)&bqkv, g_bqkv);
    cudaGetSymbolAddress((void**)&hb,   g_hb);
    cudaGetSymbolAddress((void**)&qkv,  g_qkv);
    cudaGetSymbolAddress((void**)&ab,   g_ab);
    cudaGetSymbolAddress((void**)&aob,  g_aob);
    cudaGetSymbolAddress((void**)&prt,  g_part);
    cudaGetSymbolAddress((void**)&inv,  g_inv);
    cudaGetSymbolAddress((void**)&gp,   g_gp);
    cudaGetSymbolAddress((void**)&gs,   g_gs);
    __nv_bfloat16* wob = wb + (size_t)3 * CCH * CCH;

    const size_t CN  = (size_t)CCH * NPIX;
    const size_t NN  = (size_t)NPIX * NPIX;
    const size_t CN3 = 3 * CN;
    const float scale = 1.0f / sqrtf((float)CCH);

    cudaFuncSetAttribute(bgemm_kernel<0, 0, true,  false, true,  false, false>,
                         cudaFuncAttributeMaxDynamicSharedMemorySize, SMEMSZ);
    cudaFuncSetAttribute(bgemm_kernel<1, 0, false, false, true,  true,  false>,
                         cudaFuncAttributeMaxDynamicSharedMemorySize, SMEMSZ);
    cudaFuncSetAttribute(bgemm_kernel<0, 1, false, false, true,  false, true >,
                         cudaFuncAttributeMaxDynamicSharedMemorySize, SMEMSZ);
    cudaFuncSetAttribute(bgemm_kernel<0, 0, true,  true,  false, false, false>,
                         cudaFuncAttributeMaxDynamicSharedMemorySize, SMEMSZ);

    // 0. weights -> bf16 (+ stacked qkv bias in same launch)
    cvtw_kernel<<<518, 256>>>(wq, wk, wv, wo, bq, bk, bv, wb, bqkv);

    // 1. GroupNorm (3-phase, full grid) -> bf16 h
    gn_stats1<<<512, 256>>>(x, gp);
    gn_stats2<<<1, 64>>>(gp, gs);
    gn_norm<<<512, 256>>>(x, norm_w, norm_b, gs, hb);

    // 2. merged QKV projection: Wqkv[1536,512] @ h[512,4096] -> qkv bf16
    dim3 gQKV(NPIX / BN, (3 * CCH) / BM, BATCH);
    bgemm_kernel<0, 0, true, false, true, false, false><<<gQKV, 256, SMEMSZ>>>(
        wb, CCH, 0, hb, NPIX, CN, qkv, NPIX, CN3,
        bqkv, nullptr, 0, nullptr, nullptr, CCH, 1.0f);

    // 3. scores + exp fused: P[i][j] = exp(scale * q[:,i].k[:,j]); row partials
    dim3 gScore(NPIX / BN, NPIX / BM, BATCH);
    bgemm_kernel<1, 0, false, false, true, true, false><<<gScore, 256, SMEMSZ>>>(
        qkv, NPIX, CN3, qkv + CN, NPIX, CN3, ab, NPIX, NN,
        nullptr, nullptr, 0, prt, nullptr, CCH, scale);

    // 4. row partials -> 1/rowsum
    rowinv_kernel<<<BATCH * NPIX / 256, 256>>>(prt, inv);

    // 5. ao[c,i] = (sum_j v[c,j] P[i,j]) * inv[i]  -> bf16
    dim3 gOut(NPIX / BN, CCH / BM, BATCH);
    bgemm_kernel<0, 1, false, false, true, false, true><<<gOut, 256, SMEMSZ>>>(
        qkv + 2 * CN, NPIX, CN3, ab, NPIX, NN, aob, NPIX, CN,
        nullptr, nullptr, 0, nullptr, inv, NPIX, 1.0f);

    // 6. out = x + wo @ ao + bo  (fp32 out + residual)
    bgemm_kernel<0, 0, true, true, false, false, false><<<gOut, 256, SMEMSZ>>>(
        wob, CCH, 0, aob, NPIX, CN, out, NPIX, CN,
        bo, x, CN, nullptr, nullptr, CCH, 1.0f);
}

// round 17
// speedup vs baseline: 1.2153x; 1.2153x over previous
#include <cuda_runtime.h>
#include <cuda_bf16.h>
#include <math.h>
#include <stdint.h>

// Shape fixed by reference: B=2, C=512, H=W=64 -> N=4096, 32 groups.
#define BATCH 2
#define CCH   512
#define NGRP  32
#define NPIX  4096
#define EPSV  1e-6f

// ---------------------------------------------------------------------------
// Scratch
// ---------------------------------------------------------------------------
__device__ __nv_bfloat16 g_wb  [4 * CCH * CCH];
__device__ float         g_bqkv[3 * CCH];
__device__ __nv_bfloat16 g_hb  [BATCH * CCH * NPIX];
__device__ __nv_bfloat16 g_qkv [BATCH * 3 * CCH * NPIX];
__device__ __nv_bfloat16 g_ab  [(size_t)BATCH * NPIX * NPIX];
__device__ __nv_bfloat16 g_aob [BATCH * CCH * NPIX];
__device__ float         g_part[(size_t)BATCH * NPIX * 32];
__device__ float         g_inv [BATCH * NPIX];
__device__ float2        g_gp  [64 * 8];    // groupnorm partial {sum, sumsq}
__device__ float2        g_gs  [64];        // groupnorm {mean, inv}

// ---------------------------------------------------------------------------
// Helpers
// ---------------------------------------------------------------------------
__device__ __forceinline__ float warpSum(float v) {
    #pragma unroll
    for (int o = 16; o; o >>= 1) v += __shfl_xor_sync(0xffffffffu, v, o);
    return v;
}
__device__ __forceinline__ uint32_t pack_bf16(float lo, float hi) {
    uint32_t u;
    asm("cvt.rn.bf16x2.f32 %0, %1, %2;" : "=r"(u) : "f"(hi), "f"(lo));
    return u;
}
__device__ __forceinline__ void ldsm4(uint32_t& r0, uint32_t& r1,
                                      uint32_t& r2, uint32_t& r3, uint32_t addr) {
    asm volatile("ldmatrix.sync.aligned.x4.m8n8.shared.b16 {%0,%1,%2,%3},[%4];"
                 : "=r"(r0), "=r"(r1), "=r"(r2), "=r"(r3) : "r"(addr));
}
__device__ __forceinline__ void ldsm4t(uint32_t& r0, uint32_t& r1,
                                       uint32_t& r2, uint32_t& r3, uint32_t addr) {
    asm volatile("ldmatrix.sync.aligned.x4.m8n8.trans.shared.b16 {%0,%1,%2,%3},[%4];"
                 : "=r"(r0), "=r"(r1), "=r"(r2), "=r"(r3) : "r"(addr));
}
__device__ __forceinline__ void cpasync16(uint32_t smem, const void* g) {
    asm volatile("cp.async.cg.shared.global [%0],[%1],16;" :: "r"(smem), "l"(g));
}
#define CP_COMMIT() asm volatile("cp.async.commit_group;")

// ---------------------------------------------------------------------------
// Phase 0 (fused): blocks 0..511    = groupnorm stats pass 1,
//                  blocks 512..1023 = weights fp32->bf16 (4 x 128 blocks),
//                  blocks 1024..1029 = stacked qkv bias.
// Data-independent; one launch lets them overlap. Grid = 1030.
// ---------------------------------------------------------------------------
__global__ __launch_bounds__(256) void phase0_kernel(
    const float* __restrict__ x, float2* __restrict__ gp,
    const float* __restrict__ wq, const float* __restrict__ wk,
    const float* __restrict__ wv, const float* __restrict__ wo,
    const float* __restrict__ bq, const float* __restrict__ bk,
    const float* __restrict__ bv,
    __nv_bfloat16* __restrict__ dst, float* __restrict__ bd)
{
    int b = blockIdx.x;
    int tid = threadIdx.x;
    if (b >= 1024) {                           // bias blocks (1024..1029)
        int i = (b - 1024) * 256 + tid;        // 0..1535
        bd[i] = (i < 512) ? bq[i] : (i < 1024) ? bk[i - 512] : bv[i - 1024];
        return;
    }
    if (b >= 512) {                            // weight blocks (512..1023)
        int wblk = b - 512;                    // 0..511
        int mi = wblk >> 7, blk = wblk & 127;  // mi in 0..3
        const float* src = (mi == 0) ? wq : (mi == 1) ? wk : (mi == 2) ? wv : wo;
        const float4* s4 = (const float4*)src;
        uint2* d2 = (uint2*)(dst + (size_t)mi * CCH * CCH);
        #pragma unroll
        for (int t = 0; t < 2; t++) {
            int i = blk * 512 + tid + t * 256;
            float4 v = s4[i];
            d2[i] = make_uint2(pack_bf16(v.x, v.y), pack_bf16(v.z, v.w));
        }
        return;
    }
    // groupnorm stats pass 1 (identical math to R13 gn_stats1)
    int g64 = b >> 3, slice = b & 7;
    size_t base = (size_t)g64 * 16 * NPIX + (size_t)slice * 8192;
    const float4* x4 = (const float4*)(x + base);
    float s = 0.f, ss = 0.f;
    #pragma unroll
    for (int t = 0; t < 8; t++) {
        float4 v = x4[tid + t * 256];
        s  += v.x + v.y + v.z + v.w;
        ss += v.x * v.x + v.y * v.y + v.z * v.z + v.w * v.w;
    }
    __shared__ float rs[8], rss[8];
    float ws = warpSum(s), wss = warpSum(ss);
    int lane = tid & 31, wid = tid >> 5;
    if (lane == 0) { rs[wid] = ws; rss[wid] = wss; }
    __syncthreads();
    if (tid == 0) {
        float S = 0.f, SS = 0.f;
        #pragma unroll
        for (int i = 0; i < 8; i++) { S += rs[i]; SS += rss[i]; }
        gp[b] = make_float2(S, SS);
    }
}

__global__ __launch_bounds__(64) void gn_stats2(
    const float2* __restrict__ gp, float2* __restrict__ gs)
{
    int g64 = threadIdx.x;
    float S = 0.f, SS = 0.f;
    #pragma unroll
    for (int i = 0; i < 8; i++) {
        float2 p = gp[g64 * 8 + i];
        S += p.x; SS += p.y;
    }
    const float GSZ = 16.f * NPIX;
    float mean = S / GSZ;
    float var = SS / GSZ - mean * mean;
    gs[g64] = make_float2(mean, rsqrtf(var + EPSV));
}

__global__ __launch_bounds__(256) void gn_norm(
    const float* __restrict__ x, const float* __restrict__ w,
    const float* __restrict__ b, const float2* __restrict__ gs,
    __nv_bfloat16* __restrict__ out)
{
    int bg = blockIdx.x;
    int g64 = bg >> 3, slice = bg & 7;
    int g = g64 & 31;
    size_t base = (size_t)g64 * 16 * NPIX + (size_t)slice * 8192;
    const float4* x4 = (const float4*)(x + base);
    uint2* o2 = (uint2*)(out + base);
    float2 mv = gs[g64];
    int c0 = g * 16 + slice * 2;
    float sc0 = w[c0] * mv.y,     sb0 = b[c0] - mv.x * sc0;
    float sc1 = w[c0 + 1] * mv.y, sb1 = b[c0 + 1] - mv.x * sc1;
    int tid = threadIdx.x;
    #pragma unroll
    for (int t = 0; t < 8; t++) {
        int i = tid + t * 256;
        float sc = (i < 1024) ? sc0 : sc1;
        float sb = (i < 1024) ? sb0 : sb1;
        float4 v = x4[i];
        v.x = v.x * sc + sb; v.y = v.y * sc + sb;
        v.z = v.z * sc + sb; v.w = v.w * sc + sb;
        o2[i] = make_uint2(pack_bf16(v.x, v.y), pack_bf16(v.z, v.w));
    }
}

__global__ __launch_bounds__(256) void rowinv_kernel(
    const float* __restrict__ part, float* __restrict__ inv)
{
    int r = blockIdx.x * 256 + threadIdx.x;
    const float* p = part + (size_t)r * 32;
    float s = 0.f;
    #pragma unroll
    for (int i = 0; i < 32; i++) s += p[i];
    inv[r] = 1.f / s;
}

// ---------------------------------------------------------------------------
// BF16 tensor-core GEMM, BK=64, 3-stage cp.async pipeline (depth 2) —
// EXACT R10/R13 mainloop (proven 306.7us config):
//   C[m,n] = alpha * sum_k A(m,k)*B(k,n)
//   TA/TB layouts; OBF bf16 out; BIAS +bias[m]; RES +resid
//   EXPO: C = bf16(exp(alpha*acc)) + per-row partial sums
//   SCL : epilogue multiply by scl[n]
// Block 128x128, 256 threads (8 warps, warp tile 64x32).
// smem strides (halves): k-contig [128][64] stride 72; m/n-contig [64][128]
// stride 136. Both conflict-free for LDSM.
// ---------------------------------------------------------------------------
#define BM 128
#define BN 128
#define BK 64
#define STAGES 3
#define TILE_H 9216
#define SMEMSZ (STAGES * TILE_H * 2 * 2)   // 110592 bytes

#define MMA_BF16(d, a, b)                                                     \
    asm volatile(                                                             \
        "mma.sync.aligned.m16n8k16.row.col.f32.bf16.bf16.f32 "                \
        "{%0,%1,%2,%3},{%4,%5,%6,%7},{%8,%9},{%0,%1,%2,%3};"                  \
        : "+f"(d[0]), "+f"(d[1]), "+f"(d[2]), "+f"(d[3])                      \
        : "r"(a[0]), "r"(a[1]), "r"(a[2]), "r"(a[3]), "r"(b[0]), "r"(b[1]))

template<int TA, int TB, bool BIAS, bool RES, bool OBF, bool EXPO, bool SCL>
__global__ __launch_bounds__(256) void bgemm_kernel(
    const __nv_bfloat16* __restrict__ A, int lda, size_t sA,
    const __nv_bfloat16* __restrict__ B, int ldb, size_t sB,
    void* __restrict__ Cv, int ldc, size_t sC,
    const float* __restrict__ bias,
    const float* __restrict__ resid, size_t sR,
    float* __restrict__ part, const float* __restrict__ scl,
    int K, float alpha)
{
    extern __shared__ __align__(16) uint16_t dsm[];
    uint16_t* Asm = dsm;
    uint16_t* Bsm = dsm + STAGES * TILE_H;

    int bz = blockIdx.z;
    A += (size_t)bz * sA;
    B += (size_t)bz * sB;
    if (RES) resid += (size_t)bz * sR;
    if (SCL) scl   += (size_t)bz * NPIX;

    const int m0 = blockIdx.y * BM;
    const int n0 = blockIdx.x * BN;
    const int tid = threadIdx.x;
    const int lane = tid & 31;
    const int warp = tid >> 5;
    const int wm = warp >> 2;
    const int wn = warp & 3;
    const int R  = wm * 64;
    const int CN = wn * 32;

    const uint32_t aS0 = (uint32_t)__cvta_generic_to_shared(Asm);
    const uint32_t bS0 = (uint32_t)__cvta_generic_to_shared(Bsm);

    // ---- staging: 4 x 16B chunks per operand per thread (tile = 16KB data) ----
    size_t gA[4]; int soA[4];
    size_t gB[4]; int soB[4];
    #pragma unroll
    for (int t = 0; t < 4; t++) {
        int f = tid + t * 256;                 // 0..1023 chunks
        if (TA == 0) {                         // [128][64] k-contig, stride 72
            int m = f >> 3, c8 = (f & 7) << 3;
            gA[t] = (size_t)(m0 + m) * lda + c8;
            soA[t] = m * 72 + c8;
        } else {                               // [64][128] m-contig, stride 136
            int k = f >> 4, c8 = (f & 15) << 3;
            gA[t] = (size_t)k * lda + m0 + c8;
            soA[t] = k * 136 + c8;
        }
        if (TB == 0) {                         // [64][128] n-contig, stride 136
            int k = f >> 4, c8 = (f & 15) << 3;
            gB[t] = (size_t)k * ldb + n0 + c8;
            soB[t] = k * 136 + c8;
        } else {                               // [128][64] k-contig, stride 72
            int n = f >> 3, c8 = (f & 7) << 3;
            gB[t] = (size_t)(n0 + n) * ldb + c8;
            soB[t] = n * 72 + c8;
        }
    }
    const size_t stepA = (TA == 0) ? (size_t)BK : (size_t)BK * lda;
    const size_t stepB = (TB == 0) ? (size_t)BK * ldb : (size_t)BK;

    // ---- lane-derived LDSM base offsets (halves) ----
    const int lq = lane & 7;
    const int b1 = (lane >> 3) & 1;
    const int b2 = lane >> 4;
    int aBase, bBase;
    if (TA == 0) aBase = (R + lq + 8 * b1) * 72 + 8 * b2;
    else         aBase = (lq + 8 * b2) * 136 + R + 8 * b1;
    if (TB == 0) bBase = (lq + 8 * b1) * 136 + CN + 8 * b2;
    else         bBase = (CN + lq + 8 * b2) * 72 + 8 * b1;

    float acc[4][4][4];
    #pragma unroll
    for (int i = 0; i < 4; i++)
        #pragma unroll
        for (int j = 0; j < 4; j++)
            #pragma unroll
            for (int r = 0; r < 4; r++) acc[i][j][r] = 0.f;

    const int KT = K / BK;

    // ---- prologue: async-stage tiles 0,1 ----
    #pragma unroll
    for (int s = 0; s < 2; s++) {
        #pragma unroll
        for (int t = 0; t < 4; t++) {
            cpasync16(aS0 + (s * TILE_H + soA[t]) * 2, A + gA[t] + (size_t)s * stepA);
            cpasync16(bS0 + (s * TILE_H + soB[t]) * 2, B + gB[t] + (size_t)s * stepB);
        }
        CP_COMMIT();
    }

    for (int kt = 0; kt < KT; kt++) {
        const int cur = kt % 3;
        if (kt + 1 < KT) asm volatile("cp.async.wait_group 1;");
        else             asm volatile("cp.async.wait_group 0;");
        __syncthreads();

        const uint32_t aS = aS0 + cur * (TILE_H * 2);
        const uint32_t bS = bS0 + cur * (TILE_H * 2);
        #pragma unroll
        for (int ks = 0; ks < 4; ks++) {
            uint32_t a[4][4], b[4][2];
            #pragma unroll
            for (int mt = 0; mt < 4; mt++) {
                int off = (TA == 0) ? (aBase + mt * 1152 + ks * 16)
                                    : (aBase + ks * 2176 + mt * 16);
                uint32_t addr = aS + 2 * off;
                if (TA == 0) ldsm4 (a[mt][0], a[mt][1], a[mt][2], a[mt][3], addr);
                else         ldsm4t(a[mt][0], a[mt][1], a[mt][2], a[mt][3], addr);
            }
            #pragma unroll
            for (int ntp = 0; ntp < 2; ntp++) {
                int off = (TB == 0) ? (bBase + ks * 2176 + ntp * 16)
                                    : (bBase + ntp * 1152 + ks * 16);
                uint32_t addr = bS + 2 * off;
                if (TB == 0)
                    ldsm4t(b[ntp*2][0], b[ntp*2][1], b[ntp*2+1][0], b[ntp*2+1][1], addr);
                else
                    ldsm4 (b[ntp*2][0], b[ntp*2][1], b[ntp*2+1][0], b[ntp*2+1][1], addr);
            }
            #pragma unroll
            for (int mt = 0; mt < 4; mt++)
                #pragma unroll
                for (int nt = 0; nt < 4; nt++)
                    MMA_BF16(acc[mt][nt], a[mt], b[nt]);
        }

        // stage kt+2 into buffer (kt+2)%3 (consumed at kt-1; safe after barrier)
        if (kt + 2 < KT) {
            const int nxt = (kt + 2) % 3;
            size_t ko = (size_t)(kt + 2);
            #pragma unroll
            for (int t = 0; t < 4; t++) {
                cpasync16(aS0 + (nxt * TILE_H + soA[t]) * 2, A + gA[t] + ko * stepA);
                cpasync16(bS0 + (nxt * TILE_H + soB[t]) * 2, B + gB[t] + ko * stepB);
            }
            CP_COMMIT();
        }
    }

    if (EXPO) {
        // scores epilogue: P = bf16(exp(alpha*acc)); deterministic row partials
        __syncthreads();
        float* spart = (float*)dsm;            // [128][4]
        __nv_bfloat16* Cb = (__nv_bfloat16*)Cv + (size_t)bz * sC;
        #pragma unroll
        for (int mt = 0; mt < 4; mt++) {
            int rbase = R + mt * 16 + (lane >> 2);
            #pragma unroll
            for (int h = 0; h < 2; h++) {
                int rowl = rbase + h * 8;
                int m = m0 + rowl;
                float rsum = 0.f;
                #pragma unroll
                for (int nt = 0; nt < 4; nt++) {
                    int n = n0 + CN + nt * 8 + 2 * (lane & 3);
                    float e0 = __expf(acc[mt][nt][h * 2 + 0] * alpha);
                    float e1 = __expf(acc[mt][nt][h * 2 + 1] * alpha);
                    rsum += e0 + e1;
                    *(uint32_t*)(Cb + (size_t)m * ldc + n) = pack_bf16(e0, e1);
                }
                rsum += __shfl_xor_sync(0xffffffffu, rsum, 1);
                rsum += __shfl_xor_sync(0xffffffffu, rsum, 2);
                if ((lane & 3) == 0) spart[rowl * 4 + wn] = rsum;
            }
        }
        __syncthreads();
        if (tid < 128) {
            float vv = spart[tid * 4] + spart[tid * 4 + 1]
                     + spart[tid * 4 + 2] + spart[tid * 4 + 3];
            part[((size_t)bz * NPIX + m0 + tid) * 32 + blockIdx.x] = vv;
        }
        return;
    }

    // ---- standard epilogue ----
    #pragma unroll
    for (int mt = 0; mt < 4; mt++) {
        int mA = m0 + R + mt * 16 + (lane >> 2);
        #pragma unroll
        for (int h = 0; h < 2; h++) {
            int m = mA + h * 8;
            float bi = BIAS ? bias[m] : 0.f;
            #pragma unroll
            for (int nt = 0; nt < 4; nt++) {
                int n = n0 + CN + nt * 8 + 2 * (lane & 3);
                size_t off = (size_t)m * ldc + n;
                float ox = acc[mt][nt][h * 2 + 0] * alpha + bi;
                float oy = acc[mt][nt][h * 2 + 1] * alpha + bi;
                if (SCL) { ox *= scl[n]; oy *= scl[n + 1]; }
                if (OBF) {
                    __nv_bfloat16* Cb = (__nv_bfloat16*)Cv + (size_t)bz * sC;
                    *(uint32_t*)(Cb + off) = pack_bf16(ox, oy);
                } else {
                    float* Cf = (float*)Cv + (size_t)bz * sC;
                    if (RES) {
                        float2 rr = *(const float2*)(resid + off);
                        ox += rr.x; oy += rr.y;
                    }
                    *(float2*)(Cf + off) = make_float2(ox, oy);
                }
            }
        }
    }
}

// ---------------------------------------------------------------------------
// Host launcher
// ---------------------------------------------------------------------------
extern "C" void kernel_launch(void* const* d_in, const int* in_sizes, int n_in,
                              void* d_out, int out_size)
{
    const float* x      = (const float*)d_in[0];
    const float* norm_w = (const float*)d_in[1];
    const float* norm_b = (const float*)d_in[2];
    const float* wq     = (const float*)d_in[3];
    const float* bq     = (const float*)d_in[4];
    const float* wk     = (const float*)d_in[5];
    const float* bk     = (const float*)d_in[6];
    const float* wv     = (const float*)d_in[7];
    const float* bv     = (const float*)d_in[8];
    const float* wo     = (const float*)d_in[9];
    const float* bo     = (const float*)d_in[10];
    float* out = (float*)d_out;

    __nv_bfloat16 *wb, *hb, *qkv, *ab, *aob;
    float *bqkv, *prt, *inv;
    float2 *gp, *gs;
    cudaGetSymbolAddress((void**)&wb,   g_wb);
    cudaGetSymbolAddress((void**)&bqkv, g_bqkv);
    cudaGetSymbolAddress((void**)&hb,   g_hb);
    cudaGetSymbolAddress((void**)&qkv,  g_qkv);
    cudaGetSymbolAddress((void**)&ab,   g_ab);
    cudaGetSymbolAddress((void**)&aob,  g_aob);
    cudaGetSymbolAddress((void**)&prt,  g_part);
    cudaGetSymbolAddress((void**)&inv,  g_inv);
    cudaGetSymbolAddress((void**)&gp,   g_gp);
    cudaGetSymbolAddress((void**)&gs,   g_gs);
    __nv_bfloat16* wob = wb + (size_t)3 * CCH * CCH;

    const size_t CN  = (size_t)CCH * NPIX;
    const size_t NN  = (size_t)NPIX * NPIX;
    const size_t CN3 = 3 * CN;
    const float scale = 1.0f / sqrtf((float)CCH);

    cudaFuncSetAttribute(bgemm_kernel<0, 0, true,  false, true,  false, false>,
                         cudaFuncAttributeMaxDynamicSharedMemorySize, SMEMSZ);
    cudaFuncSetAttribute(bgemm_kernel<1, 0, false, false, true,  true,  false>,
                         cudaFuncAttributeMaxDynamicSharedMemorySize, SMEMSZ);
    cudaFuncSetAttribute(bgemm_kernel<0, 1, false, false, true,  false, true >,
                         cudaFuncAttributeMaxDynamicSharedMemorySize, SMEMSZ);
    cudaFuncSetAttribute(bgemm_kernel<0, 0, true,  true,  false, false, false>,
                         cudaFuncAttributeMaxDynamicSharedMemorySize, SMEMSZ);

    // 0. fused: groupnorm stats pass1 + weights->bf16 + stacked bias
    phase0_kernel<<<1030, 256>>>(x, gp, wq, wk, wv, wo, bq, bk, bv, wb, bqkv);

    // 1. GroupNorm finish -> bf16 h
    gn_stats2<<<1, 64>>>(gp, gs);
    gn_norm<<<512, 256>>>(x, norm_w, norm_b, gs, hb);

    // 2. merged QKV projection: Wqkv[1536,512] @ h[512,4096] -> qkv bf16
    dim3 gQKV(NPIX / BN, (3 * CCH) / BM, BATCH);
    bgemm_kernel<0, 0, true, false, true, false, false><<<gQKV, 256, SMEMSZ>>>(
        wb, CCH, 0, hb, NPIX, CN, qkv, NPIX, CN3,
        bqkv, nullptr, 0, nullptr, nullptr, CCH, 1.0f);

    // 3. scores + exp fused: P[i][j] = exp(scale * q[:,i].k[:,j]); row partials
    dim3 gScore(NPIX / BN, NPIX / BM, BATCH);
    bgemm_kernel<1, 0, false, false, true, true, false><<<gScore, 256, SMEMSZ>>>(
        qkv, NPIX, CN3, qkv + CN, NPIX, CN3, ab, NPIX, NN,
        nullptr, nullptr, 0, prt, nullptr, CCH, scale);

    // 4. row partials -> 1/rowsum
    rowinv_kernel<<<BATCH * NPIX / 256, 256>>>(prt, inv);

    // 5. ao[c,i] = (sum_j v[c,j] P[i,j]) * inv[i]  -> bf16
    dim3 gOut(NPIX / BN, CCH / BM, BATCH);
    bgemm_kernel<0, 1, false, false, true, false, true><<<gOut, 256, SMEMSZ>>>(
        qkv + 2 * CN, NPIX, CN3, ab, NPIX, NN, aob, NPIX, CN,
        nullptr, nullptr, 0, nullptr, inv, NPIX, 1.0f);

    // 6. out = x + wo @ ao + bo  (fp32 out + residual)
    bgemm_kernel<0, 0, true, true, false, false, false><<<gOut, 256, SMEMSZ>>>(
        wob, CCH, 0, aob, NPIX, CN, out, NPIX, CN,
        bo, x, CN, nullptr, nullptr, CCH, 1.0f);
}